// round 11
// baseline (speedup 1.0000x reference)
#include <cuda_runtime.h>
#include <cuda_fp16.h>
#include <math.h>
#include <stdint.h>

// ---------------- problem constants ----------------
#define NS    16384
#define DIMX  3200
#define LMAX  4

__constant__ int c_offD[4] = {0, 9, 34, 83};

// fused-GEMM tables (m = 1..4), co = {512,384,256,128}
__constant__ int c_co[4]   = {512, 384, 256, 128};
__constant__ int c_Up0[4]  = {512, 1536, 2304, 2816};            // u0 segment prefix in U (u1 follows at +co)
__constant__ int c_WAo[4]  = {327680, 851968, 1146880, 1277952}; // A-weight offset (B follows at +co*co)
__constant__ int c_zoff[4] = {640, 1664, 2432, 2944};            // Z column offset of segment m

// build_w: 9 subs: m0 (640x512), then per m: A, B
__constant__ int c_wb_pref[10] = {0,327680,589824,851968,999424,1146880,1212416,1277952,1294336,1310720};
__constant__ int c_wb_K[9]     = {512,512,512,384,384,256,256,128,128};

// ---------------- device scratch ----------------
__device__ float g_J[164];
__device__ float g_DT[(size_t)NS * 164];
__device__ __half g_W[1310720];
__device__ __half g_U[(size_t)NS * 3072];
__device__ float g_Z[(size_t)NS * 3200];   // sample-major rows, final flat-IDX order

// =======================================================================
// Kernel 0: build J matrices (reference algorithm, fp64, parallel)
// =======================================================================
__global__ void build_J_kernel() {
    __shared__ double Xr[4][81], Xi[4][81], Qr[4][81], Qi[4][81];
    __shared__ double Sa[4][81], Se[4][81], St[4][81];
    int g = threadIdx.x / 96;
    int e = threadIdx.x % 96;
    int l = g + 1, d = 2*l + 1, dd = d*d;
    const double j = (double)l;
    const double SQ12 = 0.70710678118654752440;
    const double PI_D = 3.14159265358979323846;

    if (e < 81) { Xr[g][e]=0; Xi[g][e]=0; Qr[g][e]=0; Qi[g][e]=0; }
    __syncthreads();
    if (e == 0) {
        for (int i2 = 0; i2 < d-1; i2++) {
            double m  = -j + (double)i2;
            double rv = -sqrt(j*(j+1.0) - m*(m+1.0));
            Xr[g][(i2+1)*d + i2] += 0.5 * rv;
            double m2 = -j + 1.0 + (double)i2;
            double lv = sqrt(j*(j+1.0) - m2*(m2-1.0));
            Xr[g][i2*d + (i2+1)] += 0.5 * lv;
        }
        for (int i2 = 0; i2 < d; i2++) Xi[g][i2*d + i2] += (-j + (double)i2);
        for (int m = 1; m <= l; m++) {
            int r = l - m;
            Qr[g][r*d + (l+m)] = SQ12;
            Qi[g][r*d + r]     = -SQ12;
            int r2 = l + m;
            double sgn = (m & 1) ? -1.0 : 1.0;
            Qr[g][r2*d + r2]     = sgn * SQ12;
            Qi[g][r2*d + (l-m)]  = sgn * SQ12;
        }
        Qr[g][l*d + l] = 1.0;
    }
    __syncthreads();
    if (e < dd) {
        int i = e / d, jj = e % d;
        double s = 0.0;
        for (int k = 0; k < d; k++) {
            double mr = 0.0, mi = 0.0;
            for (int p = 0; p < d; p++) {
                mr += Xr[g][k*d+p]*Qr[g][p*d+jj] - Xi[g][k*d+p]*Qi[g][p*d+jj];
                mi += Xr[g][k*d+p]*Qi[g][p*d+jj] + Xi[g][k*d+p]*Qr[g][p*d+jj];
            }
            s += Qr[g][k*d+i]*mr + Qi[g][k*d+i]*mi;
        }
        Sa[g][e] = (PI_D * SQ12) * s * (1.0/1024.0);
        Se[g][e] = (i == jj) ? 1.0 : 0.0;
        St[g][e] = (i == jj) ? 1.0 : 0.0;
    }
    __syncthreads();
    for (int k = 1; k < 24; k++) {
        double v = 0.0;
        if (e < dd) {
            int i = e / d, jj = e % d;
            double s = 0.0;
            for (int p = 0; p < d; p++) s += St[g][i*d+p] * Sa[g][p*d+jj];
            v = s / (double)k;
        }
        __syncthreads();
        if (e < dd) { St[g][e] = v; Se[g][e] += v; }
        __syncthreads();
    }
    for (int s2 = 0; s2 < 10; s2++) {
        double v = 0.0;
        if (e < dd) {
            int i = e / d, jj = e % d;
            double s = 0.0;
            for (int p = 0; p < d; p++) s += Se[g][i*d+p] * Se[g][p*d+jj];
            v = s;
        }
        __syncthreads();
        if (e < dd) Se[g][e] = v;
        __syncthreads();
    }
    if (e < dd) g_J[c_offD[g] + e] = (float)Se[g][e];
}

// =======================================================================
// Kernel 1: build W (fp16): sub 0 = fc0_w (cols 128..639); per m: A then B
// =======================================================================
__global__ void build_w_kernel(const float* __restrict__ fc0_w,
                               const float* __restrict__ w1, const float* __restrict__ w2,
                               const float* __restrict__ w3, const float* __restrict__ w4) {
    int gid = blockIdx.x * blockDim.x + threadIdx.x;
    if (gid >= 1310720) return;
    int s = 0;
    #pragma unroll
    for (int q = 1; q < 9; q++) if (gid >= c_wb_pref[q]) s = q;
    int local = gid - c_wb_pref[s];
    int K = c_wb_K[s];
    int o = local / K;
    int t = local - o * K;
    float v;
    if (s == 0) {
        v = fc0_w[o * 640 + t + 128];
    } else {
        int m = (s - 1) / 2 + 1;
        int which = (s - 1) & 1;        // 0 = A, 1 = B
        const float* w = (m == 1) ? w1 : (m == 2) ? w2 : (m == 3) ? w3 : w4;
        v = which ? w[(K + o) * K + t] : w[o * K + t];
    }
    g_W[gid] = __float2half_rn(v);
}

// =======================================================================
// Kernel 2: per-sample Wigner D^T (D = Z(a) J Z(b) J)
// =======================================================================
__global__ void wigner_kernel(const float* __restrict__ R) {
    int gid = blockIdx.x * blockDim.x + threadIdx.x;
    if (gid >= NS * 4) return;
    int n = gid >> 2;
    int l = (gid & 3) + 1;
    int d = 2*l + 1;

    float vx = R[n*3 + 1], vy = R[n*3 + 2], vz = R[n*3 + 0];
    float nrm = sqrtf(vx*vx + vy*vy + vz*vz);
    nrm = fmaxf(nrm, 1e-12f);
    vx /= nrm; vy /= nrm; vz /= nrm;
    vx = fminf(fmaxf(vx, -1.f), 1.f);
    vy = fminf(fmaxf(vy, -1.f), 1.f);
    vz = fminf(fmaxf(vz, -1.f), 1.f);
    float beta  = acosf(vy);
    float alpha = atan2f(vx, vz);

    const float* J = g_J + c_offD[l-1];
    float T1[81], T2[81], Dm[81];

    for (int i = 0; i < d; i++) {
        float fr = (float)(l - i);
        float c = cosf(fr * beta), s = sinf(fr * beta);
        int ri = d - 1 - i;
        for (int jj = 0; jj < d; jj++)
            T1[i*d + jj] = c * J[i*d + jj] + s * J[ri*d + jj];
    }
    for (int i = 0; i < d; i++)
        for (int jj = 0; jj < d; jj++) {
            float s = 0.f;
            for (int k = 0; k < d; k++) s += J[i*d + k] * T1[k*d + jj];
            T2[i*d + jj] = s;
        }
    for (int i = 0; i < d; i++) {
        float fr = (float)(l - i);
        float c = cosf(fr * alpha), s = sinf(fr * alpha);
        int ri = d - 1 - i;
        for (int jj = 0; jj < d; jj++)
            Dm[i*d + jj] = c * T2[i*d + jj] + s * T2[ri*d + jj];
    }
    float* dst = g_DT + (size_t)n * 164 + c_offD[l-1];
    for (int i = 0; i < d; i++)
        for (int jj = 0; jj < d; jj++)
            dst[i*d + jj] = Dm[jj*d + i];
}

// ---------------- index decode: linear e in [0,3200) -> (m,j,l,k,i) ----------------
__device__ __forceinline__ void decode_e(int e, int& m, int& j, int& l, int& k, int& i) {
    if (e < 640) {
        m = 0; j = e; l = e >> 7; k = e & 127; i = l;
    } else {
        if (e < 1664)      { m = 1; j = e - 640;  }
        else if (e < 2432) { m = 2; j = e - 1664; }
        else if (e < 2944) { m = 3; j = e - 2432; }
        else               { m = 4; j = e - 2944; }
        int bl = j >> 8, r = j & 255;
        k = r >> 1;
        l = m + bl;
        i = (r & 1) ? (l + m) : (l - m);
    }
}

// =======================================================================
// Kernel 3: rotate x (block-per-thread), gather into fp16 u0/u1 segments
// =======================================================================
__global__ __launch_bounds__(256) void rot_gather_kernel(const float* __restrict__ x) {
    int n = blockIdx.x;
    __shared__ float xs[DIMX];
    __shared__ float xrot[DIMX];
    __shared__ float dt[164];
    const float* xr = x + (size_t)n * DIMX;
    for (int c = threadIdx.x; c < DIMX; c += 256) xs[c] = xr[c];
    for (int c = threadIdx.x; c < 164; c += 256) dt[c] = g_DT[(size_t)n * 164 + c];
    __syncthreads();

    int k = threadIdx.x & 127;
    int h = threadIdx.x >> 7;
    #define ROTBLK(D, DTO, XO) do {                                          \
        const float* xb = xs + XO + k * D;                                   \
        float xv[D];                                                         \
        _Pragma("unroll") for (int j = 0; j < D; j++) xv[j] = xb[j];         \
        _Pragma("unroll") for (int i = 0; i < D; i++) {                      \
            const float* ddp = dt + DTO + i * D;                             \
            float v = 0.f;                                                   \
            _Pragma("unroll") for (int j = 0; j < D; j++) v += ddp[j] * xv[j]; \
            xrot[XO + k * D + i] = v;                                        \
        }                                                                    \
    } while (0)
    if (h == 0) { ROTBLK(3, 0, 128);  ROTBLK(9, 83, 2048); }
    else        { ROTBLK(5, 9, 512);  ROTBLK(7, 34, 1152); }
    __syncthreads();

    // m0 segment (512 wide): diagonal entries of l=1..4 blocks, half2 stores
    {
        int j = threadIdx.x * 2;
        if (j < 512) {
            int jj = j + 128;
            int l = jj >> 7, kk = jj & 127;
            int d = 2*l + 1;
            float va = xrot[128*l*l + kk*d + l];
            float vb = xrot[128*l*l + (kk+1)*d + l];
            *(__half2*)&g_U[(size_t)n * 512 + j] = __floats2half2_rn(va, vb);
        }
    }
    // m>=1: u0 (first half of flat), u1 (second half), paired half2
    #define GATH(MM, CO, P0, P1)                                             \
    for (int tb = threadIdx.x * 2; tb < CO; tb += 512) {                     \
        int ph = tb >> 1;                                                    \
        int l0 = MM + (ph >> 7), k0 = ph & 127;                              \
        int p1 = (CO >> 1) + ph;                                             \
        int l1 = MM + (p1 >> 7), k1 = p1 & 127;                              \
        int b0 = 128*l0*l0 + k0*(2*l0 + 1);                                  \
        int b1 = 128*l1*l1 + k1*(2*l1 + 1);                                  \
        float u0a = xrot[b0 + l0 - MM], u0b = xrot[b0 + l0 + MM];            \
        float u1a = xrot[b1 + l1 - MM], u1b = xrot[b1 + l1 + MM];            \
        *(__half2*)&g_U[(size_t)NS * P0 + (size_t)n * CO + tb] = __floats2half2_rn(u0a, u0b); \
        *(__half2*)&g_U[(size_t)NS * P1 + (size_t)n * CO + tb] = __floats2half2_rn(u1a, u1b); \
    }
    GATH(1, 512, 512, 1024)
    GATH(2, 384, 1536, 1920)
    GATH(3, 256, 2304, 2560)
    GATH(4, 128, 2816, 2944)
}

// =======================================================================
// GEMM common helpers
// =======================================================================
__device__ __forceinline__ uint32_t smem_u32(const void* p) {
    uint32_t a;
    asm("{ .reg .u64 t; cvta.to.shared.u64 t, %1; cvt.u32.u64 %0, t; }" : "=r"(a) : "l"(p));
    return a;
}
#define CP_ASYNC16(dst, src) \
    asm volatile("cp.async.cg.shared.global [%0], [%1], 16;" :: "r"(dst), "l"(src) : "memory")
#define CP_COMMIT() asm volatile("cp.async.commit_group;" ::: "memory")
#define CP_WAIT1()  asm volatile("cp.async.wait_group 1;" ::: "memory")
#define CP_WAIT0()  asm volatile("cp.async.wait_group 0;" ::: "memory")
#define LDSM_X4(r0, r1, r2, r3, addr) \
    asm volatile("ldmatrix.sync.aligned.m8n8.x4.shared.b16 {%0,%1,%2,%3}, [%4];" \
                 : "=r"(r0), "=r"(r1), "=r"(r2), "=r"(r3) : "r"(addr))
#define HADD2U(d, a, b) \
    asm("add.rn.f16x2 %0, %1, %2;" : "=r"(d) : "r"(a), "r"(b))

__device__ __forceinline__ void hmma16816(float* c, const uint32_t* a, const uint32_t* b) {
    asm volatile(
        "mma.sync.aligned.m16n8k16.row.col.f32.f16.f16.f32 "
        "{%0,%1,%2,%3}, {%4,%5,%6,%7}, {%8,%9}, {%0,%1,%2,%3};"
        : "+f"(c[0]), "+f"(c[1]), "+f"(c[2]), "+f"(c[3])
        : "r"(a[0]), "r"(a[1]), "r"(a[2]), "r"(a[3]), "r"(b[0]), "r"(b[1]));
}

// =======================================================================
// Kernel 4a: m0 GEMM (N=640, K=512), 128x128 CTA tile, C rows stride 3200
// =======================================================================
__global__ __launch_bounds__(256) void hmma_m0_kernel() {
    extern __shared__ __align__(1024) char dsm[];
    uint32_t sbase = smem_u32(dsm);

    int tid = threadIdx.x;
    int wid = tid >> 5;
    int lane = tid & 31;

    const int K = 512;
    int id = blockIdx.x;
    int bcolt = id % 5, browt = id / 5;
    int brow = browt << 7, bcol = bcolt << 7;

    const __half* A = g_U;            // m0 input, [NS, 512]
    const __half* B = g_W;            // [640, 512]

    int r = tid >> 1, q2 = tid & 1;
    const char* gA = (const char*)(A + (size_t)(brow + r) * K + q2 * 32);
    const char* gB = (const char*)(B + (size_t)(bcol + r) * K + q2 * 32);
    uint32_t sts[4];
    #pragma unroll
    for (int i = 0; i < 4; i++) {
        uint32_t off = (uint32_t)r * 128u + (uint32_t)(q2 * 4 + i) * 16u;
        sts[i] = off ^ ((off >> 3) & 0x70);
    }

    int wm = wid >> 1, wn = wid & 1;
    uint32_t a_row[2], a_rx[2];
    #pragma unroll
    for (int mt = 0; mt < 2; mt++) {
        int row = wm * 32 + mt * 16 + (lane & 15);
        a_row[mt] = (uint32_t)row * 128u;
        a_rx[mt] = (uint32_t)(row & 7) << 4;
    }
    uint32_t a_cb = ((lane >> 4) & 1) * 16u;
    int nloc = (lane & 7) + ((lane & 16) >> 1);
    uint32_t b_row[4], b_rx[4];
    #pragma unroll
    for (int nt4 = 0; nt4 < 4; nt4++) {
        int nrow = wn * 64 + nt4 * 16 + nloc;
        b_row[nt4] = (uint32_t)nrow * 128u;
        b_rx[nt4] = (uint32_t)(nrow & 7) << 4;
    }
    uint32_t b_cb = ((lane >> 3) & 1) * 16u;

    float acc[2][8][4];
    #pragma unroll
    for (int mt = 0; mt < 2; mt++)
        #pragma unroll
        for (int nt = 0; nt < 8; nt++)
            #pragma unroll
            for (int e = 0; e < 4; e++) acc[mt][nt][e] = 0.f;

    const int NC = 8;
    #pragma unroll
    for (int p = 0; p < 2; p++) {
        uint32_t aS = sbase + (uint32_t)p * 32768u;
        uint32_t bS = aS + 16384u;
        const char* Ap = gA + (size_t)p * 128;
        const char* Bp = gB + (size_t)p * 128;
        #pragma unroll
        for (int i = 0; i < 4; i++) {
            CP_ASYNC16(aS + sts[i], Ap + i * 16);
            CP_ASYNC16(bS + sts[i], Bp + i * 16);
        }
        CP_COMMIT();
    }

    for (int c = 0; c < NC; ++c) {
        if (c + 1 < NC) CP_WAIT1(); else CP_WAIT0();
        __syncthreads();
        if (c + 2 < NC) {
            int st = (c + 2) % 3;
            uint32_t aS = sbase + (uint32_t)st * 32768u;
            uint32_t bS = aS + 16384u;
            const char* Ap = gA + (size_t)(c + 2) * 128;
            const char* Bp = gB + (size_t)(c + 2) * 128;
            #pragma unroll
            for (int i = 0; i < 4; i++) {
                CP_ASYNC16(aS + sts[i], Ap + i * 16);
                CP_ASYNC16(bS + sts[i], Bp + i * 16);
            }
            CP_COMMIT();
        }
        int cst = c % 3;
        uint32_t aS = sbase + (uint32_t)cst * 32768u;
        uint32_t bS = aS + 16384u;
        #pragma unroll
        for (int kq = 0; kq < 4; kq++) {
            uint32_t kb = (uint32_t)kq * 32u;
            uint32_t afr[2][4];
            #pragma unroll
            for (int mt = 0; mt < 2; mt++)
                LDSM_X4(afr[mt][0], afr[mt][1], afr[mt][2], afr[mt][3],
                        aS + a_row[mt] + ((a_cb + kb) ^ a_rx[mt]));
            uint32_t bfr[4][4];
            #pragma unroll
            for (int nt4 = 0; nt4 < 4; nt4++)
                LDSM_X4(bfr[nt4][0], bfr[nt4][1], bfr[nt4][2], bfr[nt4][3],
                        bS + b_row[nt4] + ((b_cb + kb) ^ b_rx[nt4]));
            #pragma unroll
            for (int mt = 0; mt < 2; mt++)
                #pragma unroll
                for (int nt = 0; nt < 8; nt++)
                    hmma16816(acc[mt][nt], afr[mt], &bfr[nt >> 1][(nt & 1) * 2]);
        }
    }

    int g2 = lane >> 2, t2 = lane & 3;
    #pragma unroll
    for (int mt = 0; mt < 2; mt++) {
        #pragma unroll
        for (int nt = 0; nt < 8; nt++) {
            int row0 = brow + wm * 32 + mt * 16 + g2;
            int col = bcol + wn * 64 + nt * 8 + t2 * 2;
            float2 v0 = make_float2(acc[mt][nt][0], acc[mt][nt][1]);
            float2 v1 = make_float2(acc[mt][nt][2], acc[mt][nt][3]);
            *(float2*)(g_Z + (size_t)row0 * 3200 + col) = v0;
            *(float2*)(g_Z + (size_t)(row0 + 8) * 3200 + col) = v1;
        }
    }
}

// =======================================================================
// Kernel 4b: fused Karatsuba GEMM for m=1..4
//   CTA tile 128 samples x 64 cols; 3 accumulator sets (A*u0, B*u1, S*uS)
//   with S, uS built in-register via f16x2 adds. Epilogue writes final
//   flat-order re/im into g_Z rows (stride 3200).
// =======================================================================
__global__ __launch_bounds__(256) void hmma_fused_kernel() {
    extern __shared__ __align__(1024) char dsm[];
    uint32_t sbase = smem_u32(dsm);

    int tid = threadIdx.x;
    int wid = tid >> 5;
    int lane = tid & 31;

    // tile decode: 2560 CTAs = 128 row-tiles x 20 col-tiles (m1:8, m2:6, m3:4, m4:2)
    int id = blockIdx.x;
    int ct = id % 20;
    int rowt = id / 20;
    int m, cb;
    if (ct < 8)       { m = 1; cb = ct; }
    else if (ct < 14) { m = 2; cb = ct - 8; }
    else if (ct < 18) { m = 3; cb = ct - 14; }
    else              { m = 4; cb = ct - 18; }
    int co = c_co[m-1];
    int K = co;
    int brow = rowt << 7, bcol = cb << 6;
    const __half* Au0 = g_U + (size_t)NS * c_Up0[m-1];
    const __half* Au1 = Au0 + (size_t)NS * co;
    const __half* WA = g_W + c_WAo[m-1];
    const __half* WB = WA + co * co;
    int zoff = c_zoff[m-1];

    // loaders: A tiles (128 rows x 128B): 2 thr/row x 4 chunks of 16B
    int r = tid >> 1, q2 = tid & 1;
    const char* gA0 = (const char*)(Au0 + (size_t)(brow + r) * K + q2 * 32);
    const char* gA1 = (const char*)(Au1 + (size_t)(brow + r) * K + q2 * 32);
    uint32_t stsA[4];
    #pragma unroll
    for (int i = 0; i < 4; i++) {
        uint32_t off = (uint32_t)r * 128u + (uint32_t)(q2 * 4 + i) * 16u;
        stsA[i] = off ^ ((off >> 3) & 0x70);
    }
    // B tiles (64 rows x 128B): 4 thr/row x 2 chunks of 16B -> +q3*16 HALVES (32B)
    int r3 = tid >> 2, q3 = tid & 3;
    const char* gBA = (const char*)(WA + (size_t)(bcol + r3) * K + q3 * 16);
    const char* gBB = (const char*)(WB + (size_t)(bcol + r3) * K + q3 * 16);
    uint32_t stsB[2];
    #pragma unroll
    for (int i = 0; i < 2; i++) {
        uint32_t off = (uint32_t)r3 * 128u + (uint32_t)q3 * 32u + (uint32_t)i * 16u;
        stsB[i] = off ^ ((off >> 3) & 0x70);
    }

    // warp layout: 32 rows x 32 cols per warp
    int wm = wid >> 1, wn = wid & 1;
    uint32_t a_row[2], a_rx[2];
    #pragma unroll
    for (int mt = 0; mt < 2; mt++) {
        int row = wm * 32 + mt * 16 + (lane & 15);
        a_row[mt] = (uint32_t)row * 128u;
        a_rx[mt] = (uint32_t)(row & 7) << 4;
    }
    uint32_t a_cb = ((lane >> 4) & 1) * 16u;
    int nloc = (lane & 7) + ((lane & 16) >> 1);
    uint32_t b_row[2], b_rx[2];
    #pragma unroll
    for (int gg = 0; gg < 2; gg++) {
        int nrow = wn * 32 + gg * 16 + nloc;
        b_row[gg] = (uint32_t)nrow * 128u;
        b_rx[gg] = (uint32_t)(nrow & 7) << 4;
    }
    uint32_t b_cb = ((lane >> 3) & 1) * 16u;

    float acc1[2][4][4], acc2[2][4][4], acc3[2][4][4];
    #pragma unroll
    for (int mt = 0; mt < 2; mt++)
        #pragma unroll
        for (int nt = 0; nt < 4; nt++)
            #pragma unroll
            for (int e = 0; e < 4; e++) { acc1[mt][nt][e] = 0.f; acc2[mt][nt][e] = 0.f; acc3[mt][nt][e] = 0.f; }

    int NC = K >> 6;
    // stage: [u0 16K][u1 16K][wA 8K][wB 8K] = 48K, 3 stages
    #define LOADSTAGE(ST, C) do {                                            \
        uint32_t sb2 = sbase + (uint32_t)(ST) * 49152u;                      \
        const char* pa0 = gA0 + (size_t)(C) * 128;                           \
        const char* pa1 = gA1 + (size_t)(C) * 128;                           \
        _Pragma("unroll")                                                    \
        for (int i = 0; i < 4; i++) {                                        \
            CP_ASYNC16(sb2 + stsA[i], pa0 + i * 16);                         \
            CP_ASYNC16(sb2 + 16384u + stsA[i], pa1 + i * 16);                \
        }                                                                    \
        const char* pba = gBA + (size_t)(C) * 128;                           \
        const char* pbb = gBB + (size_t)(C) * 128;                           \
        _Pragma("unroll")                                                    \
        for (int i = 0; i < 2; i++) {                                        \
            CP_ASYNC16(sb2 + 32768u + stsB[i], pba + i * 16);                \
            CP_ASYNC16(sb2 + 40960u + stsB[i], pbb + i * 16);                \
        }                                                                    \
        CP_COMMIT();                                                         \
    } while (0)

    LOADSTAGE(0, 0);
    LOADSTAGE(1, 1);

    for (int c = 0; c < NC; ++c) {
        if (c + 1 < NC) CP_WAIT1(); else CP_WAIT0();
        __syncthreads();
        if (c + 2 < NC) LOADSTAGE((c + 2) % 3, c + 2);
        uint32_t sb2 = sbase + (uint32_t)(c % 3) * 49152u;
        #pragma unroll
        for (int kq = 0; kq < 4; kq++) {
            uint32_t kb = (uint32_t)kq * 32u;
            uint32_t a0[2][4], a1[2][4], aS[2][4];
            #pragma unroll
            for (int mt = 0; mt < 2; mt++) {
                uint32_t ao = a_row[mt] + ((a_cb + kb) ^ a_rx[mt]);
                LDSM_X4(a0[mt][0], a0[mt][1], a0[mt][2], a0[mt][3], sb2 + ao);
                LDSM_X4(a1[mt][0], a1[mt][1], a1[mt][2], a1[mt][3], sb2 + 16384u + ao);
                #pragma unroll
                for (int r4 = 0; r4 < 4; r4++) HADD2U(aS[mt][r4], a0[mt][r4], a1[mt][r4]);
            }
            #pragma unroll
            for (int gg = 0; gg < 2; gg++) {
                uint32_t bo = b_row[gg] + ((b_cb + kb) ^ b_rx[gg]);
                uint32_t bA[4], bB[4], bS[4];
                LDSM_X4(bA[0], bA[1], bA[2], bA[3], sb2 + 32768u + bo);
                LDSM_X4(bB[0], bB[1], bB[2], bB[3], sb2 + 40960u + bo);
                #pragma unroll
                for (int r4 = 0; r4 < 4; r4++) HADD2U(bS[r4], bA[r4], bB[r4]);
                #pragma unroll
                for (int mt = 0; mt < 2; mt++)
                    #pragma unroll
                    for (int hh = 0; hh < 2; hh++) {
                        int nt = gg * 2 + hh;
                        hmma16816(acc1[mt][nt], a0[mt], &bA[hh * 2]);
                        hmma16816(acc2[mt][nt], a1[mt], &bB[hh * 2]);
                        hmma16816(acc3[mt][nt], aS[mt], &bS[hh * 2]);
                    }
            }
        }
    }

    // epilogue: re = m1 - m2, im = m3 - m1 - m2; flat: re at zoff+t, im at zoff+co+t
    int g2 = lane >> 2, t2 = lane & 3;
    #pragma unroll
    for (int mt = 0; mt < 2; mt++) {
        #pragma unroll
        for (int nt = 0; nt < 4; nt++) {
            int row0 = brow + wm * 32 + mt * 16 + g2;
            int col = bcol + wn * 32 + nt * 8 + t2 * 2;
            float re0 = acc1[mt][nt][0] - acc2[mt][nt][0];
            float re1 = acc1[mt][nt][1] - acc2[mt][nt][1];
            float im0 = acc3[mt][nt][0] - acc1[mt][nt][0] - acc2[mt][nt][0];
            float im1 = acc3[mt][nt][1] - acc1[mt][nt][1] - acc2[mt][nt][1];
            float* Z0 = g_Z + (size_t)row0 * 3200;
            *(float2*)(Z0 + zoff + col) = make_float2(re0, re1);
            *(float2*)(Z0 + zoff + co + col) = make_float2(im0, im1);
            float re2 = acc1[mt][nt][2] - acc2[mt][nt][2];
            float re3 = acc1[mt][nt][3] - acc2[mt][nt][3];
            float im2 = acc3[mt][nt][2] - acc1[mt][nt][2] - acc2[mt][nt][2];
            float im3 = acc3[mt][nt][3] - acc1[mt][nt][3] - acc2[mt][nt][3];
            float* Z1 = g_Z + (size_t)(row0 + 8) * 3200;
            *(float2*)(Z1 + zoff + col) = make_float2(re2, re3);
            *(float2*)(Z1 + zoff + co + col) = make_float2(im2, im3);
        }
    }
}

// =======================================================================
// Kernel 5: map flat Z row (+bias) into block layout, rotate back, write out
// =======================================================================
__global__ __launch_bounds__(256) void scatter_rot_kernel(const float* __restrict__ fc0_b,
                                                          float* __restrict__ out) {
    int n = blockIdx.x;
    __shared__ float pre[DIMX];
    __shared__ float ob[DIMX];
    __shared__ float dt[164];
    for (int c = threadIdx.x; c < 164; c += 256) dt[c] = g_DT[(size_t)n * 164 + c];

    const float* zrow = g_Z + (size_t)n * 3200;
    for (int e = threadIdx.x; e < DIMX; e += 256) {
        int m, j, l, k, i;
        decode_e(e, m, j, l, k, i);
        float v = zrow[e];
        if (m == 0) v += fc0_b[j];
        pre[128*l*l + k*(2*l + 1) + i] = v;
    }
    __syncthreads();

    int k = threadIdx.x & 127;
    int h = threadIdx.x >> 7;
    #define ROTO(D, DTO, XO) do {                                            \
        const float* pb = pre + XO + k * D;                                  \
        float xv[D];                                                         \
        _Pragma("unroll") for (int j = 0; j < D; j++) xv[j] = pb[j];         \
        _Pragma("unroll") for (int i = 0; i < D; i++) {                      \
            const float* ddp = dt + DTO + i * D;                             \
            float v = 0.f;                                                   \
            _Pragma("unroll") for (int j = 0; j < D; j++) v += ddp[j] * xv[j]; \
            ob[XO + k * D + i] = v;                                          \
        }                                                                    \
    } while (0)
    if (h == 0) {
        for (int c = threadIdx.x; c < 128; c += 128) ob[c] = pre[c];
        ROTO(3, 0, 128);  ROTO(9, 83, 2048);
    } else {
        ROTO(5, 9, 512);  ROTO(7, 34, 1152);
    }
    __syncthreads();

    float* orow = out + (size_t)n * DIMX;
    for (int c = threadIdx.x; c < DIMX; c += 256) orow[c] = ob[c];
}

// =======================================================================
// launch
// =======================================================================
extern "C" void kernel_launch(void* const* d_in, const int* in_sizes, int n_in,
                              void* d_out, int out_size) {
    const float* x     = (const float*)d_in[0];
    const float* R     = (const float*)d_in[1];
    const float* fc0_w = (const float*)d_in[2];
    const float* fc0_b = (const float*)d_in[3];
    const float* w1    = (const float*)d_in[4];
    const float* w2    = (const float*)d_in[5];
    const float* w3    = (const float*)d_in[6];
    const float* w4    = (const float*)d_in[7];
    float* out = (float*)d_out;

    build_J_kernel<<<1, 384>>>();
    build_w_kernel<<<(1310720 + 255) / 256, 256>>>(fc0_w, w1, w2, w3, w4);
    wigner_kernel<<<(NS * 4 + 127) / 128, 128>>>(R);
    rot_gather_kernel<<<NS, 256>>>(x);

    cudaFuncSetAttribute(hmma_m0_kernel,
                         cudaFuncAttributeMaxDynamicSharedMemorySize, 98304);
    hmma_m0_kernel<<<640, 256, 98304>>>();

    cudaFuncSetAttribute(hmma_fused_kernel,
                         cudaFuncAttributeMaxDynamicSharedMemorySize, 147456);
    hmma_fused_kernel<<<2560, 256, 147456>>>();

    scatter_rot_kernel<<<NS, 256>>>(fc0_b, out);
}

// round 12
// speedup vs baseline: 1.1084x; 1.1084x over previous
#include <cuda_runtime.h>
#include <cuda_fp16.h>
#include <math.h>
#include <stdint.h>

// ---------------- problem constants ----------------
#define NS    16384
#define DIMX  3200
#define LMAX  4

__constant__ int c_offD[4] = {0, 9, 34, 83};

// 13 sub-GEMMs: 0: m0 (N=640, K=512); per m=1..4: A, B, A+B (co x co)
__constant__ int cg_tileStart[14] = {0,640,1152,1664,2176,2560,2944,3328,3584,3840,4096,4224,4352,4480};
__constant__ int cg_Ksub[13]  = {512,512,512,512,384,384,384,256,256,256,128,128,128};
__constant__ int cg_Nsub[13]  = {640,512,512,512,384,384,384,256,256,256,128,128,128};
__constant__ int cg_Up[13]    = {0,512,1024,1536,2048,2432,2816,3200,3456,3712,3968,4096,4224};   // U prefixes (total 4352)
__constant__ int cg_Zp[13]    = {0,640,1152,1664,2176,2560,2944,3328,3584,3840,4096,4224,4352};   // Z prefixes (total 4480)
__constant__ int cg_Wpref[14] = {0,327680,589824,851968,1114112,1261568,1409024,1556480,1622016,1687552,1753088,1769472,1785856,1802240};

// ---------------- device scratch ----------------
__device__ float g_J[164];
__device__ __half g_W[1802240];
__device__ __half g_U[(size_t)NS * 4352];
__device__ __half g_Z[(size_t)NS * 4480];     // fp16 GEMM outputs

// =======================================================================
// Kernel 0: build J matrices (reference algorithm, fp64, parallel)
// =======================================================================
__global__ void build_J_kernel() {
    __shared__ double Xr[4][81], Xi[4][81], Qr[4][81], Qi[4][81];
    __shared__ double Sa[4][81], Se[4][81], St[4][81];
    int g = threadIdx.x / 96;
    int e = threadIdx.x % 96;
    int l = g + 1, d = 2*l + 1, dd = d*d;
    const double j = (double)l;
    const double SQ12 = 0.70710678118654752440;
    const double PI_D = 3.14159265358979323846;

    if (e < 81) { Xr[g][e]=0; Xi[g][e]=0; Qr[g][e]=0; Qi[g][e]=0; }
    __syncthreads();
    if (e == 0) {
        for (int i2 = 0; i2 < d-1; i2++) {
            double m  = -j + (double)i2;
            double rv = -sqrt(j*(j+1.0) - m*(m+1.0));
            Xr[g][(i2+1)*d + i2] += 0.5 * rv;
            double m2 = -j + 1.0 + (double)i2;
            double lv = sqrt(j*(j+1.0) - m2*(m2-1.0));
            Xr[g][i2*d + (i2+1)] += 0.5 * lv;
        }
        for (int i2 = 0; i2 < d; i2++) Xi[g][i2*d + i2] += (-j + (double)i2);
        for (int m = 1; m <= l; m++) {
            int r = l - m;
            Qr[g][r*d + (l+m)] = SQ12;
            Qi[g][r*d + r]     = -SQ12;
            int r2 = l + m;
            double sgn = (m & 1) ? -1.0 : 1.0;
            Qr[g][r2*d + r2]     = sgn * SQ12;
            Qi[g][r2*d + (l-m)]  = sgn * SQ12;
        }
        Qr[g][l*d + l] = 1.0;
    }
    __syncthreads();
    if (e < dd) {
        int i = e / d, jj = e % d;
        double s = 0.0;
        for (int k = 0; k < d; k++) {
            double mr = 0.0, mi = 0.0;
            for (int p = 0; p < d; p++) {
                mr += Xr[g][k*d+p]*Qr[g][p*d+jj] - Xi[g][k*d+p]*Qi[g][p*d+jj];
                mi += Xr[g][k*d+p]*Qi[g][p*d+jj] + Xi[g][k*d+p]*Qr[g][p*d+jj];
            }
            s += Qr[g][k*d+i]*mr + Qi[g][k*d+i]*mi;
        }
        Sa[g][e] = (PI_D * SQ12) * s * (1.0/1024.0);
        Se[g][e] = (i == jj) ? 1.0 : 0.0;
        St[g][e] = (i == jj) ? 1.0 : 0.0;
    }
    __syncthreads();
    for (int k = 1; k < 24; k++) {
        double v = 0.0;
        if (e < dd) {
            int i = e / d, jj = e % d;
            double s = 0.0;
            for (int p = 0; p < d; p++) s += St[g][i*d+p] * Sa[g][p*d+jj];
            v = s / (double)k;
        }
        __syncthreads();
        if (e < dd) { St[g][e] = v; Se[g][e] += v; }
        __syncthreads();
    }
    for (int s2 = 0; s2 < 10; s2++) {
        double v = 0.0;
        if (e < dd) {
            int i = e / d, jj = e % d;
            double s = 0.0;
            for (int p = 0; p < d; p++) s += Se[g][i*d+p] * Se[g][p*d+jj];
            v = s;
        }
        __syncthreads();
        if (e < dd) Se[g][e] = v;
        __syncthreads();
    }
    if (e < dd) g_J[c_offD[g] + e] = (float)Se[g][e];
}

// =======================================================================
// Kernel 1: build W (fp16): sub 0 = fc0_w cols 128..639; subs 3m-2..3m: A, B, A+B
// =======================================================================
__global__ void build_w_kernel(const float* __restrict__ fc0_w,
                               const float* __restrict__ w1, const float* __restrict__ w2,
                               const float* __restrict__ w3, const float* __restrict__ w4) {
    int gid = blockIdx.x * blockDim.x + threadIdx.x;
    if (gid >= 1802240) return;
    int s = 0;
    #pragma unroll
    for (int q = 1; q < 13; q++) if (gid >= cg_Wpref[q]) s = q;
    int local = gid - cg_Wpref[s];
    int K = cg_Ksub[s];
    int o = local / K;
    int t = local - o * K;
    float v;
    if (s == 0) {
        v = fc0_w[o * 640 + t + 128];   // skip zero l=0 K-block
    } else {
        int m = (s - 1) / 3 + 1;
        int which = (s - 1) % 3;
        const float* w = (m == 1) ? w1 : (m == 2) ? w2 : (m == 3) ? w3 : w4;
        if (which == 0)      v = w[o * K + t];
        else if (which == 1) v = w[(K + o) * K + t];
        else                 v = w[o * K + t] + w[(K + o) * K + t];
    }
    g_W[gid] = __float2half_rn(v);
}

// =======================================================================
// In-CTA Wigner D^T: warps 0-3 compute l = wid+1 into dt[] (t1 scratch).
// Identical op sequence to the former wigner_kernel -> bit-exact dt.
// Requires __syncthreads() after call before dt is read by other warps.
// =======================================================================
__device__ __forceinline__ void compute_DT_smem(int n, const float* __restrict__ R,
                                                float* dt, float* t1, int tid) {
    int wid = tid >> 5, lane = tid & 31;
    if (wid >= 4) return;
    int l = wid + 1, d = 2*l + 1, dd = d*d;

    float vx = R[n*3 + 1], vy = R[n*3 + 2], vz = R[n*3 + 0];
    float nrm = sqrtf(vx*vx + vy*vy + vz*vz);
    nrm = fmaxf(nrm, 1e-12f);
    vx /= nrm; vy /= nrm; vz /= nrm;
    vx = fminf(fmaxf(vx, -1.f), 1.f);
    vy = fminf(fmaxf(vy, -1.f), 1.f);
    vz = fminf(fmaxf(vz, -1.f), 1.f);
    float beta  = acosf(vy);
    float alpha = atan2f(vx, vz);

    const float* J = g_J + c_offD[l-1];
    float* T1 = t1 + c_offD[l-1];
    float* DD = dt + c_offD[l-1];

    // T1 = Z(beta) @ J
    for (int e = lane; e < dd; e += 32) {
        int i = e / d, jj = e - i * d;
        float fr = (float)(l - i);
        float c = cosf(fr * beta), s = sinf(fr * beta);
        T1[e] = c * J[e] + s * J[(d - 1 - i)*d + jj];
    }
    __syncwarp();
    // T2 = J @ T1  (store into DD)
    for (int e = lane; e < dd; e += 32) {
        int i = e / d, jj = e - i * d;
        float s2 = 0.f;
        for (int k = 0; k < d; k++) s2 += J[i*d + k] * T1[k*d + jj];
        DD[e] = s2;
    }
    __syncwarp();
    // D = Z(alpha) @ T2 (to regs), then store D^T
    float dv[3]; int cnt = 0;
    for (int e = lane; e < dd; e += 32) {
        int i = e / d, jj = e - i * d;
        float fr = (float)(l - i);
        float c = cosf(fr * alpha), s = sinf(fr * alpha);
        dv[cnt++] = c * DD[i*d + jj] + s * DD[(d - 1 - i)*d + jj];
    }
    __syncwarp();
    cnt = 0;
    for (int e = lane; e < dd; e += 32) {
        int i = e / d, jj = e - i * d;
        DD[jj*d + i] = dv[cnt++];
    }
}

// =======================================================================
// Kernel 3: rotate x (block-per-thread), gather into fp16 sub-GEMM inputs
// =======================================================================
__global__ __launch_bounds__(256) void rot_gather_kernel(const float* __restrict__ x,
                                                         const float* __restrict__ R) {
    int n = blockIdx.x;
    __shared__ float xs[DIMX];
    __shared__ float xrot[DIMX];
    __shared__ float dt[164];
    __shared__ float t1s[164];
    const float* xr = x + (size_t)n * DIMX;
    for (int c = threadIdx.x; c < DIMX; c += 256) xs[c] = xr[c];
    compute_DT_smem(n, R, dt, t1s, threadIdx.x);
    __syncthreads();

    int k = threadIdx.x & 127;
    int h = threadIdx.x >> 7;
    #define ROTBLK(D, DTO, XO) do {                                          \
        const float* xb = xs + XO + k * D;                                   \
        float xv[D];                                                         \
        _Pragma("unroll") for (int j = 0; j < D; j++) xv[j] = xb[j];         \
        _Pragma("unroll") for (int i = 0; i < D; i++) {                      \
            const float* ddp = dt + DTO + i * D;                             \
            float v = 0.f;                                                   \
            _Pragma("unroll") for (int j = 0; j < D; j++) v += ddp[j] * xv[j]; \
            xrot[XO + k * D + i] = v;                                        \
        }                                                                    \
    } while (0)
    if (h == 0) { ROTBLK(3, 0, 128);  ROTBLK(9, 83, 2048); }
    else        { ROTBLK(5, 9, 512);  ROTBLK(7, 34, 1152); }
    __syncthreads();

    // m0 segment (512 wide): diagonal entries of l=1..4 blocks
    for (int j = threadIdx.x; j < 512; j += 256) {
        int jj = j + 128;
        int l = jj >> 7, kk = jj & 127;
        g_U[(size_t)n * 512 + j] = __float2half_rn(xrot[128*l*l + kk*(2*l + 1) + l]);
    }
    #define GATH(MM, CO, P0, P1, P2)                                         \
    for (int t = threadIdx.x; t < CO; t += 256) {                            \
        int c0 = t & 1, ph = t >> 1;                                         \
        int p1 = (CO >> 1) + ph;                                             \
        int l0 = MM + (ph >> 7), k0 = ph & 127;                              \
        int l1 = MM + (p1 >> 7), k1 = p1 & 127;                              \
        int i0 = c0 ? (l0 + MM) : (l0 - MM);                                 \
        int i1 = c0 ? (l1 + MM) : (l1 - MM);                                 \
        float u0 = xrot[128*l0*l0 + k0*(2*l0 + 1) + i0];                     \
        float u1 = xrot[128*l1*l1 + k1*(2*l1 + 1) + i1];                     \
        g_U[(size_t)NS * P0 + (size_t)n * CO + t] = __float2half_rn(u0);     \
        g_U[(size_t)NS * P1 + (size_t)n * CO + t] = __float2half_rn(u1);     \
        g_U[(size_t)NS * P2 + (size_t)n * CO + t] = __float2half_rn(u0 + u1);\
    }
    GATH(1, 512, 512, 1024, 1536)
    GATH(2, 384, 2048, 2432, 2816)
    GATH(3, 256, 3200, 3456, 3712)
    GATH(4, 128, 3968, 4096, 4224)
}

// =======================================================================
// Kernel 4: HMMA fp16 GEMM over 13 sub-GEMMs (C[NxK tiles], K chunks 64)
// =======================================================================
__device__ __forceinline__ uint32_t smem_u32(const void* p) {
    uint32_t a;
    asm("{ .reg .u64 t; cvta.to.shared.u64 t, %1; cvt.u32.u64 %0, t; }" : "=r"(a) : "l"(p));
    return a;
}
#define CP_ASYNC16(dst, src) \
    asm volatile("cp.async.cg.shared.global [%0], [%1], 16;" :: "r"(dst), "l"(src) : "memory")
#define CP_COMMIT() asm volatile("cp.async.commit_group;" ::: "memory")
#define CP_WAIT1()  asm volatile("cp.async.wait_group 1;" ::: "memory")
#define CP_WAIT0()  asm volatile("cp.async.wait_group 0;" ::: "memory")
#define LDSM_X4(r0, r1, r2, r3, addr) \
    asm volatile("ldmatrix.sync.aligned.m8n8.x4.shared.b16 {%0,%1,%2,%3}, [%4];" \
                 : "=r"(r0), "=r"(r1), "=r"(r2), "=r"(r3) : "r"(addr))

__device__ __forceinline__ void hmma16816(float* c, const uint32_t* a, const uint32_t* b) {
    asm volatile(
        "mma.sync.aligned.m16n8k16.row.col.f32.f16.f16.f32 "
        "{%0,%1,%2,%3}, {%4,%5,%6,%7}, {%8,%9}, {%0,%1,%2,%3};"
        : "+f"(c[0]), "+f"(c[1]), "+f"(c[2]), "+f"(c[3])
        : "r"(a[0]), "r"(a[1]), "r"(a[2]), "r"(a[3]), "r"(b[0]), "r"(b[1]));
}

__global__ __launch_bounds__(256) void hmma_gemm_all_kernel() {
    extern __shared__ __align__(1024) char dsm[];
    uint32_t sbase = smem_u32(dsm);

    int tid = threadIdx.x;
    int wid = tid >> 5;
    int lane = tid & 31;

    // ---- tile decode ----
    int id = blockIdx.x;
    int s = 0;
    #pragma unroll
    for (int q = 1; q < 13; q++) if (id >= cg_tileStart[q]) s = q;
    int local = id - cg_tileStart[s];
    int K = cg_Ksub[s];
    int N = cg_Nsub[s];
    int gx = N >> 7;
    int bcolt = local % gx, browt = local / gx;
    int brow = browt << 7, bcol = bcolt << 7;

    const __half* A = g_U + (size_t)NS * cg_Up[s];
    const __half* B = g_W + cg_Wpref[s];
    __half* C = g_Z + (size_t)NS * cg_Zp[s];

    // ---- global->smem: 2 threads/row, 4x16B each ----
    int r = tid >> 1, q2 = tid & 1;
    const char* gA = (const char*)(A + (size_t)(brow + r) * K + q2 * 32);
    const char* gB = (const char*)(B + (size_t)(bcol + r) * K + q2 * 32);
    uint32_t sts[4];
    #pragma unroll
    for (int i = 0; i < 4; i++) {
        uint32_t off = (uint32_t)r * 128u + (uint32_t)(q2 * 4 + i) * 16u;
        sts[i] = off ^ ((off >> 3) & 0x70);
    }

    // ---- per-warp compute layout ----
    int wm = wid >> 1, wn = wid & 1;
    uint32_t a_row[2], a_rx[2];
    #pragma unroll
    for (int mt = 0; mt < 2; mt++) {
        int row = wm * 32 + mt * 16 + (lane & 15);
        a_row[mt] = (uint32_t)row * 128u;
        a_rx[mt] = (uint32_t)(row & 7) << 4;
    }
    uint32_t a_cb = ((lane >> 4) & 1) * 16u;
    int nloc = (lane & 7) + ((lane & 16) >> 1);
    uint32_t b_row[4], b_rx[4];
    #pragma unroll
    for (int nt4 = 0; nt4 < 4; nt4++) {
        int nrow = wn * 64 + nt4 * 16 + nloc;
        b_row[nt4] = (uint32_t)nrow * 128u;
        b_rx[nt4] = (uint32_t)(nrow & 7) << 4;
    }
    uint32_t b_cb = ((lane >> 3) & 1) * 16u;

    float acc[2][8][4];
    #pragma unroll
    for (int mt = 0; mt < 2; mt++)
        #pragma unroll
        for (int nt = 0; nt < 8; nt++)
            #pragma unroll
            for (int e = 0; e < 4; e++) acc[mt][nt][e] = 0.f;

    int NC = K >> 6;

    // prologue: chunks 0,1 into stages 0,1
    #pragma unroll
    for (int p = 0; p < 2; p++) {
        uint32_t aS = sbase + (uint32_t)p * 32768u;
        uint32_t bS = aS + 16384u;
        const char* Ap = gA + (size_t)p * 128;
        const char* Bp = gB + (size_t)p * 128;
        #pragma unroll
        for (int i = 0; i < 4; i++) {
            CP_ASYNC16(aS + sts[i], Ap + i * 16);
            CP_ASYNC16(bS + sts[i], Bp + i * 16);
        }
        CP_COMMIT();
    }

    for (int c = 0; c < NC; ++c) {
        if (c + 1 < NC) CP_WAIT1(); else CP_WAIT0();
        __syncthreads();
        if (c + 2 < NC) {
            int st = (c + 2) % 3;
            uint32_t aS = sbase + (uint32_t)st * 32768u;
            uint32_t bS = aS + 16384u;
            const char* Ap = gA + (size_t)(c + 2) * 128;
            const char* Bp = gB + (size_t)(c + 2) * 128;
            #pragma unroll
            for (int i = 0; i < 4; i++) {
                CP_ASYNC16(aS + sts[i], Ap + i * 16);
                CP_ASYNC16(bS + sts[i], Bp + i * 16);
            }
            CP_COMMIT();
        }
        int cst = c % 3;
        uint32_t aS = sbase + (uint32_t)cst * 32768u;
        uint32_t bS = aS + 16384u;
        #pragma unroll
        for (int kq = 0; kq < 4; kq++) {
            uint32_t kb = (uint32_t)kq * 32u;
            uint32_t afr[2][4];
            #pragma unroll
            for (int mt = 0; mt < 2; mt++)
                LDSM_X4(afr[mt][0], afr[mt][1], afr[mt][2], afr[mt][3],
                        aS + a_row[mt] + ((a_cb + kb) ^ a_rx[mt]));
            uint32_t bfr[4][4];
            #pragma unroll
            for (int nt4 = 0; nt4 < 4; nt4++)
                LDSM_X4(bfr[nt4][0], bfr[nt4][1], bfr[nt4][2], bfr[nt4][3],
                        bS + b_row[nt4] + ((b_cb + kb) ^ b_rx[nt4]));
            #pragma unroll
            for (int mt = 0; mt < 2; mt++)
                #pragma unroll
                for (int nt = 0; nt < 8; nt++)
                    hmma16816(acc[mt][nt], afr[mt], &bfr[nt >> 1][(nt & 1) * 2]);
        }
    }

    // epilogue: fp16 stores (C row stride = N)
    int g2 = lane >> 2, t2 = lane & 3;
    #pragma unroll
    for (int mt = 0; mt < 2; mt++) {
        #pragma unroll
        for (int nt = 0; nt < 8; nt++) {
            int row0 = brow + wm * 32 + mt * 16 + g2;
            int col = bcol + wn * 64 + nt * 8 + t2 * 2;
            __half2 h0 = __floats2half2_rn(acc[mt][nt][0], acc[mt][nt][1]);
            __half2 h1 = __floats2half2_rn(acc[mt][nt][2], acc[mt][nt][3]);
            *(__half2*)(C + (size_t)row0 * N + col) = h0;
            *(__half2*)(C + (size_t)(row0 + 8) * N + col) = h1;
        }
    }
}

// =======================================================================
// Kernel 5: combine Karatsuba fp16 outputs (+bias), rotate back (shared),
//           coalesced write out
// =======================================================================
__global__ __launch_bounds__(256) void scatter_rot_kernel(const float* __restrict__ fc0_b,
                                                          const float* __restrict__ R,
                                                          float* __restrict__ out) {
    int n = blockIdx.x;
    __shared__ float pre[DIMX];
    __shared__ float ob[DIMX];
    __shared__ float dt[164];
    __shared__ float t1s[164];

    compute_DT_smem(n, R, dt, t1s, threadIdx.x);

    for (int j = threadIdx.x; j < 640; j += 256) {
        int l = j >> 7, k = j & 127;
        pre[128*l*l + k*(2*l + 1) + l] = __half2float(g_Z[(size_t)n * 640 + j]) + fc0_b[j];
    }
    #define SCAT(MM, CO, P0, P1, P2)                                         \
    for (int t = threadIdx.x; t < CO; t += 256) {                            \
        float v1 = __half2float(g_Z[(size_t)NS * P0 + (size_t)n * CO + t]);  \
        float v2 = __half2float(g_Z[(size_t)NS * P1 + (size_t)n * CO + t]);  \
        float v3 = __half2float(g_Z[(size_t)NS * P2 + (size_t)n * CO + t]);  \
        float re = v1 - v2, im = v3 - v1 - v2;                               \
        int c0 = t & 1, ph = t >> 1;                                         \
        int p1 = (CO >> 1) + ph;                                             \
        int l0 = MM + (ph >> 7), k0 = ph & 127;                              \
        int l1 = MM + (p1 >> 7), k1 = p1 & 127;                              \
        int i0 = c0 ? (l0 + MM) : (l0 - MM);                                 \
        int i1 = c0 ? (l1 + MM) : (l1 - MM);                                 \
        pre[128*l0*l0 + k0*(2*l0 + 1) + i0] = re;                            \
        pre[128*l1*l1 + k1*(2*l1 + 1) + i1] = im;                            \
    }
    SCAT(1, 512, 640, 1152, 1664)
    SCAT(2, 384, 2176, 2560, 2944)
    SCAT(3, 256, 3328, 3584, 3840)
    SCAT(4, 128, 4096, 4224, 4352)
    __syncthreads();

    int k = threadIdx.x & 127;
    int h = threadIdx.x >> 7;
    #define ROTO(D, DTO, XO) do {                                            \
        const float* pb = pre + XO + k * D;                                  \
        float xv[D];                                                         \
        _Pragma("unroll") for (int j = 0; j < D; j++) xv[j] = pb[j];         \
        _Pragma("unroll") for (int i = 0; i < D; i++) {                      \
            const float* ddp = dt + DTO + i * D;                             \
            float v = 0.f;                                                   \
            _Pragma("unroll") for (int j = 0; j < D; j++) v += ddp[j] * xv[j]; \
            ob[XO + k * D + i] = v;                                          \
        }                                                                    \
    } while (0)
    if (h == 0) {
        for (int c = threadIdx.x; c < 128; c += 128) ob[c] = pre[c];
        ROTO(3, 0, 128);  ROTO(9, 83, 2048);
    } else {
        ROTO(5, 9, 512);  ROTO(7, 34, 1152);
    }
    __syncthreads();

    float* orow = out + (size_t)n * DIMX;
    for (int c = threadIdx.x; c < DIMX; c += 256) orow[c] = ob[c];
}

// =======================================================================
// launch
// =======================================================================
extern "C" void kernel_launch(void* const* d_in, const int* in_sizes, int n_in,
                              void* d_out, int out_size) {
    const float* x     = (const float*)d_in[0];
    const float* R     = (const float*)d_in[1];
    const float* fc0_w = (const float*)d_in[2];
    const float* fc0_b = (const float*)d_in[3];
    const float* w1    = (const float*)d_in[4];
    const float* w2    = (const float*)d_in[5];
    const float* w3    = (const float*)d_in[6];
    const float* w4    = (const float*)d_in[7];
    float* out = (float*)d_out;

    build_J_kernel<<<1, 384>>>();
    build_w_kernel<<<(1802240 + 255) / 256, 256>>>(fc0_w, w1, w2, w3, w4);
    rot_gather_kernel<<<NS, 256>>>(x, R);

    cudaFuncSetAttribute(hmma_gemm_all_kernel,
                         cudaFuncAttributeMaxDynamicSharedMemorySize, 98304);
    hmma_gemm_all_kernel<<<4480, 256, 98304>>>();

    scatter_rot_kernel<<<NS, 256>>>(fc0_b, R, out);
}

// round 13
// speedup vs baseline: 1.3711x; 1.2370x over previous
#include <cuda_runtime.h>
#include <cuda_fp16.h>
#include <math.h>
#include <stdint.h>

// ---------------- problem constants ----------------
#define NS    16384
#define DIMX  3200
#define LMAX  4

__constant__ int c_offD[4] = {0, 9, 34, 83};

// 13 sub-GEMMs: 0: m0 (N=640, K=512); per m=1..4: A, B, A+B (co x co)
__constant__ int cg_tileStart[14] = {0,640,1152,1664,2176,2560,2944,3328,3584,3840,4096,4224,4352,4480};
__constant__ int cg_Ksub[13]  = {512,512,512,512,384,384,384,256,256,256,128,128,128};
__constant__ int cg_Nsub[13]  = {640,512,512,512,384,384,384,256,256,256,128,128,128};
__constant__ int cg_Up[13]    = {0,512,1024,1536,2048,2432,2816,3200,3456,3712,3968,4096,4224};
__constant__ int cg_Zp[13]    = {0,640,1152,1664,2176,2560,2944,3328,3584,3840,4096,4224,4352};
__constant__ int cg_Wpref[14] = {0,327680,589824,851968,1114112,1261568,1409024,1556480,1622016,1687552,1753088,1769472,1785856,1802240};

// ---------------- device scratch ----------------
__device__ float g_J[164];
__device__ __half g_W[1802240];
__device__ __half g_U[(size_t)NS * 4352];
__device__ __half g_Z[(size_t)NS * 4480];     // fp16 GEMM outputs

// =======================================================================
// Kernel 0: build J matrices (reference algorithm, fp64, parallel)
// =======================================================================
__global__ void build_J_kernel() {
    __shared__ double Xr[4][81], Xi[4][81], Qr[4][81], Qi[4][81];
    __shared__ double Sa[4][81], Se[4][81], St[4][81];
    int g = threadIdx.x / 96;
    int e = threadIdx.x % 96;
    int l = g + 1, d = 2*l + 1, dd = d*d;
    const double j = (double)l;
    const double SQ12 = 0.70710678118654752440;
    const double PI_D = 3.14159265358979323846;

    if (e < 81) { Xr[g][e]=0; Xi[g][e]=0; Qr[g][e]=0; Qi[g][e]=0; }
    __syncthreads();
    if (e == 0) {
        for (int i2 = 0; i2 < d-1; i2++) {
            double m  = -j + (double)i2;
            double rv = -sqrt(j*(j+1.0) - m*(m+1.0));
            Xr[g][(i2+1)*d + i2] += 0.5 * rv;
            double m2 = -j + 1.0 + (double)i2;
            double lv = sqrt(j*(j+1.0) - m2*(m2-1.0));
            Xr[g][i2*d + (i2+1)] += 0.5 * lv;
        }
        for (int i2 = 0; i2 < d; i2++) Xi[g][i2*d + i2] += (-j + (double)i2);
        for (int m = 1; m <= l; m++) {
            int r = l - m;
            Qr[g][r*d + (l+m)] = SQ12;
            Qi[g][r*d + r]     = -SQ12;
            int r2 = l + m;
            double sgn = (m & 1) ? -1.0 : 1.0;
            Qr[g][r2*d + r2]     = sgn * SQ12;
            Qi[g][r2*d + (l-m)]  = sgn * SQ12;
        }
        Qr[g][l*d + l] = 1.0;
    }
    __syncthreads();
    if (e < dd) {
        int i = e / d, jj = e % d;
        double s = 0.0;
        for (int k = 0; k < d; k++) {
            double mr = 0.0, mi = 0.0;
            for (int p = 0; p < d; p++) {
                mr += Xr[g][k*d+p]*Qr[g][p*d+jj] - Xi[g][k*d+p]*Qi[g][p*d+jj];
                mi += Xr[g][k*d+p]*Qi[g][p*d+jj] + Xi[g][k*d+p]*Qr[g][p*d+jj];
            }
            s += Qr[g][k*d+i]*mr + Qi[g][k*d+i]*mi;
        }
        Sa[g][e] = (PI_D * SQ12) * s * (1.0/1024.0);
        Se[g][e] = (i == jj) ? 1.0 : 0.0;
        St[g][e] = (i == jj) ? 1.0 : 0.0;
    }
    __syncthreads();
    for (int k = 1; k < 24; k++) {
        double v = 0.0;
        if (e < dd) {
            int i = e / d, jj = e % d;
            double s = 0.0;
            for (int p = 0; p < d; p++) s += St[g][i*d+p] * Sa[g][p*d+jj];
            v = s / (double)k;
        }
        __syncthreads();
        if (e < dd) { St[g][e] = v; Se[g][e] += v; }
        __syncthreads();
    }
    for (int s2 = 0; s2 < 10; s2++) {
        double v = 0.0;
        if (e < dd) {
            int i = e / d, jj = e % d;
            double s = 0.0;
            for (int p = 0; p < d; p++) s += Se[g][i*d+p] * Se[g][p*d+jj];
            v = s;
        }
        __syncthreads();
        if (e < dd) Se[g][e] = v;
        __syncthreads();
    }
    if (e < dd) g_J[c_offD[g] + e] = (float)Se[g][e];
}

// =======================================================================
// Kernel 1: build W (fp16): sub 0 = fc0_w cols 128..639; subs 3m-2..3m: A, B, A+B
// =======================================================================
__global__ void build_w_kernel(const float* __restrict__ fc0_w,
                               const float* __restrict__ w1, const float* __restrict__ w2,
                               const float* __restrict__ w3, const float* __restrict__ w4) {
    int gid = blockIdx.x * blockDim.x + threadIdx.x;
    if (gid >= 1802240) return;
    int s = 0;
    #pragma unroll
    for (int q = 1; q < 13; q++) if (gid >= cg_Wpref[q]) s = q;
    int local = gid - cg_Wpref[s];
    int K = cg_Ksub[s];
    int o = local / K;
    int t = local - o * K;
    float v;
    if (s == 0) {
        v = fc0_w[o * 640 + t + 128];
    } else {
        int m = (s - 1) / 3 + 1;
        int which = (s - 1) % 3;
        const float* w = (m == 1) ? w1 : (m == 2) ? w2 : (m == 3) ? w3 : w4;
        if (which == 0)      v = w[o * K + t];
        else if (which == 1) v = w[(K + o) * K + t];
        else                 v = w[o * K + t] + w[(K + o) * K + t];
    }
    g_W[gid] = __float2half_rn(v);
}

// =======================================================================
// In-CTA Wigner D^T: warps 0-3 compute l = wid+1 into dt[] (t1 scratch).
// =======================================================================
__device__ __forceinline__ void compute_DT_smem(int n, const float* __restrict__ R,
                                                float* dt, float* t1, int tid) {
    int wid = tid >> 5, lane = tid & 31;
    if (wid >= 4) return;
    int l = wid + 1, d = 2*l + 1, dd = d*d;

    float vx = R[n*3 + 1], vy = R[n*3 + 2], vz = R[n*3 + 0];
    float nrm = sqrtf(vx*vx + vy*vy + vz*vz);
    nrm = fmaxf(nrm, 1e-12f);
    vx /= nrm; vy /= nrm; vz /= nrm;
    vx = fminf(fmaxf(vx, -1.f), 1.f);
    vy = fminf(fmaxf(vy, -1.f), 1.f);
    vz = fminf(fmaxf(vz, -1.f), 1.f);
    float beta  = acosf(vy);
    float alpha = atan2f(vx, vz);

    const float* J = g_J + c_offD[l-1];
    float* T1 = t1 + c_offD[l-1];
    float* DD = dt + c_offD[l-1];

    for (int e = lane; e < dd; e += 32) {
        int i = e / d, jj = e - i * d;
        float fr = (float)(l - i);
        float c = cosf(fr * beta), s = sinf(fr * beta);
        T1[e] = c * J[e] + s * J[(d - 1 - i)*d + jj];
    }
    __syncwarp();
    for (int e = lane; e < dd; e += 32) {
        int i = e / d, jj = e - i * d;
        float s2 = 0.f;
        for (int k = 0; k < d; k++) s2 += J[i*d + k] * T1[k*d + jj];
        DD[e] = s2;
    }
    __syncwarp();
    float dv[3]; int cnt = 0;
    for (int e = lane; e < dd; e += 32) {
        int i = e / d, jj = e - i * d;
        float fr = (float)(l - i);
        float c = cosf(fr * alpha), s = sinf(fr * alpha);
        dv[cnt++] = c * DD[i*d + jj] + s * DD[(d - 1 - i)*d + jj];
    }
    __syncwarp();
    cnt = 0;
    for (int e = lane; e < dd; e += 32) {
        int i = e / d, jj = e - i * d;
        DD[jj*d + i] = dv[cnt++];
    }
}

// =======================================================================
// Kernel 3: rotate x in-place (block-per-thread), gather fp16 inputs (half2)
// =======================================================================
__global__ __launch_bounds__(256) void rot_gather_kernel(const float* __restrict__ x,
                                                         const float* __restrict__ R) {
    int n = blockIdx.x;
    __shared__ float xs[DIMX];
    __shared__ float dt[164];
    __shared__ float t1s[164];
    const float4* xr4 = (const float4*)(x + (size_t)n * DIMX);
    for (int c = threadIdx.x; c < DIMX/4; c += 256) ((float4*)xs)[c] = xr4[c];
    compute_DT_smem(n, R, dt, t1s, threadIdx.x);
    __syncthreads();

    int k = threadIdx.x & 127;
    int h = threadIdx.x >> 7;
    // in-place rotation: each thread owns its whole (l,k) block
    #define ROTBLK(D, DTO, XO) do {                                          \
        float* xb = xs + XO + k * D;                                         \
        float xv[D];                                                         \
        _Pragma("unroll") for (int j = 0; j < D; j++) xv[j] = xb[j];         \
        _Pragma("unroll") for (int i = 0; i < D; i++) {                      \
            const float* ddp = dt + DTO + i * D;                             \
            float v = 0.f;                                                   \
            _Pragma("unroll") for (int j = 0; j < D; j++) v += ddp[j] * xv[j]; \
            xb[i] = v;                                                       \
        }                                                                    \
    } while (0)
    if (h == 0) { ROTBLK(3, 0, 128);  ROTBLK(9, 83, 2048); }
    else        { ROTBLK(5, 9, 512);  ROTBLK(7, 34, 1152); }
    __syncthreads();

    // m0 segment (512 wide): diagonal entries of l=1..4 blocks, half2
    {
        int j = threadIdx.x * 2;
        if (j < 512) {
            int jj = j + 128;
            int l = jj >> 7, kk = jj & 127;
            int d = 2*l + 1;
            float va = xs[128*l*l + kk*d + l];
            float vb = xs[128*l*l + (kk+1)*d + l];
            *(__half2*)&g_U[(size_t)n * 512 + j] = __floats2half2_rn(va, vb);
        }
    }
    // m>=1: u0 / u1 / u0+u1, half2-paired (even/odd flat positions share (l,k))
    #define GATH(MM, CO, P0, P1, P2)                                         \
    for (int tb = threadIdx.x * 2; tb < CO; tb += 512) {                     \
        int ph = tb >> 1;                                                    \
        int l0 = MM + (ph >> 7), k0 = ph & 127;                              \
        int p1 = (CO >> 1) + ph;                                             \
        int l1 = MM + (p1 >> 7), k1 = p1 & 127;                              \
        int b0 = 128*l0*l0 + k0*(2*l0 + 1);                                  \
        int b1 = 128*l1*l1 + k1*(2*l1 + 1);                                  \
        float u0a = xs[b0 + l0 - MM], u0b = xs[b0 + l0 + MM];                \
        float u1a = xs[b1 + l1 - MM], u1b = xs[b1 + l1 + MM];                \
        *(__half2*)&g_U[(size_t)NS * P0 + (size_t)n * CO + tb] = __floats2half2_rn(u0a, u0b); \
        *(__half2*)&g_U[(size_t)NS * P1 + (size_t)n * CO + tb] = __floats2half2_rn(u1a, u1b); \
        *(__half2*)&g_U[(size_t)NS * P2 + (size_t)n * CO + tb] = __floats2half2_rn(u0a + u1a, u0b + u1b); \
    }
    GATH(1, 512, 512, 1024, 1536)
    GATH(2, 384, 2048, 2432, 2816)
    GATH(3, 256, 3200, 3456, 3712)
    GATH(4, 128, 3968, 4096, 4224)
}

// =======================================================================
// Kernel 4: HMMA fp16 GEMM over 13 sub-GEMMs (unchanged from round 12)
// =======================================================================
__device__ __forceinline__ uint32_t smem_u32(const void* p) {
    uint32_t a;
    asm("{ .reg .u64 t; cvta.to.shared.u64 t, %1; cvt.u32.u64 %0, t; }" : "=r"(a) : "l"(p));
    return a;
}
#define CP_ASYNC16(dst, src) \
    asm volatile("cp.async.cg.shared.global [%0], [%1], 16;" :: "r"(dst), "l"(src) : "memory")
#define CP_COMMIT() asm volatile("cp.async.commit_group;" ::: "memory")
#define CP_WAIT1()  asm volatile("cp.async.wait_group 1;" ::: "memory")
#define CP_WAIT0()  asm volatile("cp.async.wait_group 0;" ::: "memory")
#define LDSM_X4(r0, r1, r2, r3, addr) \
    asm volatile("ldmatrix.sync.aligned.m8n8.x4.shared.b16 {%0,%1,%2,%3}, [%4];" \
                 : "=r"(r0), "=r"(r1), "=r"(r2), "=r"(r3) : "r"(addr))

__device__ __forceinline__ void hmma16816(float* c, const uint32_t* a, const uint32_t* b) {
    asm volatile(
        "mma.sync.aligned.m16n8k16.row.col.f32.f16.f16.f32 "
        "{%0,%1,%2,%3}, {%4,%5,%6,%7}, {%8,%9}, {%0,%1,%2,%3};"
        : "+f"(c[0]), "+f"(c[1]), "+f"(c[2]), "+f"(c[3])
        : "r"(a[0]), "r"(a[1]), "r"(a[2]), "r"(a[3]), "r"(b[0]), "r"(b[1]));
}

__global__ __launch_bounds__(256) void hmma_gemm_all_kernel() {
    extern __shared__ __align__(1024) char dsm[];
    uint32_t sbase = smem_u32(dsm);

    int tid = threadIdx.x;
    int wid = tid >> 5;
    int lane = tid & 31;

    int id = blockIdx.x;
    int s = 0;
    #pragma unroll
    for (int q = 1; q < 13; q++) if (id >= cg_tileStart[q]) s = q;
    int local = id - cg_tileStart[s];
    int K = cg_Ksub[s];
    int N = cg_Nsub[s];
    int gx = N >> 7;
    int bcolt = local % gx, browt = local / gx;
    int brow = browt << 7, bcol = bcolt << 7;

    const __half* A = g_U + (size_t)NS * cg_Up[s];
    const __half* B = g_W + cg_Wpref[s];
    __half* C = g_Z + (size_t)NS * cg_Zp[s];

    int r = tid >> 1, q2 = tid & 1;
    const char* gA = (const char*)(A + (size_t)(brow + r) * K + q2 * 32);
    const char* gB = (const char*)(B + (size_t)(bcol + r) * K + q2 * 32);
    uint32_t sts[4];
    #pragma unroll
    for (int i = 0; i < 4; i++) {
        uint32_t off = (uint32_t)r * 128u + (uint32_t)(q2 * 4 + i) * 16u;
        sts[i] = off ^ ((off >> 3) & 0x70);
    }

    int wm = wid >> 1, wn = wid & 1;
    uint32_t a_row[2], a_rx[2];
    #pragma unroll
    for (int mt = 0; mt < 2; mt++) {
        int row = wm * 32 + mt * 16 + (lane & 15);
        a_row[mt] = (uint32_t)row * 128u;
        a_rx[mt] = (uint32_t)(row & 7) << 4;
    }
    uint32_t a_cb = ((lane >> 4) & 1) * 16u;
    int nloc = (lane & 7) + ((lane & 16) >> 1);
    uint32_t b_row[4], b_rx[4];
    #pragma unroll
    for (int nt4 = 0; nt4 < 4; nt4++) {
        int nrow = wn * 64 + nt4 * 16 + nloc;
        b_row[nt4] = (uint32_t)nrow * 128u;
        b_rx[nt4] = (uint32_t)(nrow & 7) << 4;
    }
    uint32_t b_cb = ((lane >> 3) & 1) * 16u;

    float acc[2][8][4];
    #pragma unroll
    for (int mt = 0; mt < 2; mt++)
        #pragma unroll
        for (int nt = 0; nt < 8; nt++)
            #pragma unroll
            for (int e = 0; e < 4; e++) acc[mt][nt][e] = 0.f;

    int NC = K >> 6;

    #pragma unroll
    for (int p = 0; p < 2; p++) {
        uint32_t aS = sbase + (uint32_t)p * 32768u;
        uint32_t bS = aS + 16384u;
        const char* Ap = gA + (size_t)p * 128;
        const char* Bp = gB + (size_t)p * 128;
        #pragma unroll
        for (int i = 0; i < 4; i++) {
            CP_ASYNC16(aS + sts[i], Ap + i * 16);
            CP_ASYNC16(bS + sts[i], Bp + i * 16);
        }
        CP_COMMIT();
    }

    for (int c = 0; c < NC; ++c) {
        if (c + 1 < NC) CP_WAIT1(); else CP_WAIT0();
        __syncthreads();
        if (c + 2 < NC) {
            int st = (c + 2) % 3;
            uint32_t aS = sbase + (uint32_t)st * 32768u;
            uint32_t bS = aS + 16384u;
            const char* Ap = gA + (size_t)(c + 2) * 128;
            const char* Bp = gB + (size_t)(c + 2) * 128;
            #pragma unroll
            for (int i = 0; i < 4; i++) {
                CP_ASYNC16(aS + sts[i], Ap + i * 16);
                CP_ASYNC16(bS + sts[i], Bp + i * 16);
            }
            CP_COMMIT();
        }
        int cst = c % 3;
        uint32_t aS = sbase + (uint32_t)cst * 32768u;
        uint32_t bS = aS + 16384u;
        #pragma unroll
        for (int kq = 0; kq < 4; kq++) {
            uint32_t kb = (uint32_t)kq * 32u;
            uint32_t afr[2][4];
            #pragma unroll
            for (int mt = 0; mt < 2; mt++)
                LDSM_X4(afr[mt][0], afr[mt][1], afr[mt][2], afr[mt][3],
                        aS + a_row[mt] + ((a_cb + kb) ^ a_rx[mt]));
            uint32_t bfr[4][4];
            #pragma unroll
            for (int nt4 = 0; nt4 < 4; nt4++)
                LDSM_X4(bfr[nt4][0], bfr[nt4][1], bfr[nt4][2], bfr[nt4][3],
                        bS + b_row[nt4] + ((b_cb + kb) ^ b_rx[nt4]));
            #pragma unroll
            for (int mt = 0; mt < 2; mt++)
                #pragma unroll
                for (int nt = 0; nt < 8; nt++)
                    hmma16816(acc[mt][nt], afr[mt], &bfr[nt >> 1][(nt & 1) * 2]);
        }
    }

    int g2 = lane >> 2, t2 = lane & 3;
    #pragma unroll
    for (int mt = 0; mt < 2; mt++) {
        #pragma unroll
        for (int nt = 0; nt < 8; nt++) {
            int row0 = brow + wm * 32 + mt * 16 + g2;
            int col = bcol + wn * 64 + nt * 8 + t2 * 2;
            __half2 h0 = __floats2half2_rn(acc[mt][nt][0], acc[mt][nt][1]);
            __half2 h1 = __floats2half2_rn(acc[mt][nt][2], acc[mt][nt][3]);
            *(__half2*)(C + (size_t)row0 * N + col) = h0;
            *(__half2*)(C + (size_t)(row0 + 8) * N + col) = h1;
        }
    }
}

// =======================================================================
// Kernel 5: combine fp16 Karatsuba outputs (+bias), rotate in place, write out
// =======================================================================
__global__ __launch_bounds__(256) void scatter_rot_kernel(const float* __restrict__ fc0_b,
                                                          const float* __restrict__ R,
                                                          float* __restrict__ out) {
    int n = blockIdx.x;
    __shared__ float pre[DIMX];
    __shared__ float dt[164];
    __shared__ float t1s[164];

    compute_DT_smem(n, R, dt, t1s, threadIdx.x);

    // m0: half2 reads, scalar placement
    for (int j = threadIdx.x * 2; j < 640; j += 512) {
        __half2 hz = *(const __half2*)&g_Z[(size_t)n * 640 + j];
        int l = j >> 7, k = j & 127;
        int base = 128*l*l;
        int d = 2*l + 1;
        pre[base + k*d + l]       = __low2float(hz)  + fc0_b[j];
        pre[base + (k+1)*d + l]   = __high2float(hz) + fc0_b[j+1];
    }
    // m>=1: half2 reads of v1,v2,v3; re/im pairs share (l,k)
    #define SCAT(MM, CO, P0, P1, P2)                                         \
    for (int tb = threadIdx.x * 2; tb < CO; tb += 512) {                     \
        __half2 h1 = *(const __half2*)&g_Z[(size_t)NS * P0 + (size_t)n * CO + tb]; \
        __half2 h2 = *(const __half2*)&g_Z[(size_t)NS * P1 + (size_t)n * CO + tb]; \
        __half2 h3 = *(const __half2*)&g_Z[(size_t)NS * P2 + (size_t)n * CO + tb]; \
        float v1a = __low2float(h1), v1b = __high2float(h1);                 \
        float v2a = __low2float(h2), v2b = __high2float(h2);                 \
        float v3a = __low2float(h3), v3b = __high2float(h3);                 \
        float rea = v1a - v2a, reb = v1b - v2b;                              \
        float ima = v3a - v1a - v2a, imb = v3b - v1b - v2b;                  \
        int ph = tb >> 1;                                                    \
        int p1 = (CO >> 1) + ph;                                             \
        int l0 = MM + (ph >> 7), k0 = ph & 127;                              \
        int l1 = MM + (p1 >> 7), k1 = p1 & 127;                              \
        int b0 = 128*l0*l0 + k0*(2*l0 + 1);                                  \
        int b1 = 128*l1*l1 + k1*(2*l1 + 1);                                  \
        pre[b0 + l0 - MM] = rea;                                             \
        pre[b0 + l0 + MM] = reb;                                             \
        pre[b1 + l1 - MM] = ima;                                             \
        pre[b1 + l1 + MM] = imb;                                             \
    }
    SCAT(1, 512, 640, 1152, 1664)
    SCAT(2, 384, 2176, 2560, 2944)
    SCAT(3, 256, 3328, 3584, 3840)
    SCAT(4, 128, 4096, 4224, 4352)
    __syncthreads();

    // in-place inverse rotation (thread owns block); l=0 block untouched
    int k = threadIdx.x & 127;
    int h = threadIdx.x >> 7;
    #define ROTO(D, DTO, XO) do {                                            \
        float* pb = pre + XO + k * D;                                        \
        float xv[D];                                                         \
        _Pragma("unroll") for (int j = 0; j < D; j++) xv[j] = pb[j];         \
        _Pragma("unroll") for (int i = 0; i < D; i++) {                      \
            const float* ddp = dt + DTO + i * D;                             \
            float v = 0.f;                                                   \
            _Pragma("unroll") for (int j = 0; j < D; j++) v += ddp[j] * xv[j]; \
            pb[i] = v;                                                       \
        }                                                                    \
    } while (0)
    if (h == 0) { ROTO(3, 0, 128);  ROTO(9, 83, 2048); }
    else        { ROTO(5, 9, 512);  ROTO(7, 34, 1152); }
    __syncthreads();

    // coalesced float4 copy to global
    float4* orow4 = (float4*)(out + (size_t)n * DIMX);
    for (int c = threadIdx.x; c < DIMX/4; c += 256) orow4[c] = ((const float4*)pre)[c];
}

// =======================================================================
// launch
// =======================================================================
extern "C" void kernel_launch(void* const* d_in, const int* in_sizes, int n_in,
                              void* d_out, int out_size) {
    const float* x     = (const float*)d_in[0];
    const float* R     = (const float*)d_in[1];
    const float* fc0_w = (const float*)d_in[2];
    const float* fc0_b = (const float*)d_in[3];
    const float* w1    = (const float*)d_in[4];
    const float* w2    = (const float*)d_in[5];
    const float* w3    = (const float*)d_in[6];
    const float* w4    = (const float*)d_in[7];
    float* out = (float*)d_out;

    build_J_kernel<<<1, 384>>>();
    build_w_kernel<<<(1802240 + 255) / 256, 256>>>(fc0_w, w1, w2, w3, w4);
    rot_gather_kernel<<<NS, 256>>>(x, R);

    cudaFuncSetAttribute(hmma_gemm_all_kernel,
                         cudaFuncAttributeMaxDynamicSharedMemorySize, 98304);
    hmma_gemm_all_kernel<<<4480, 256, 98304>>>();

    scatter_rot_kernel<<<NS, 256>>>(fc0_b, R, out);
}